// round 10
// baseline (speedup 1.0000x reference)
#include <cuda_runtime.h>

// mean(cumsum(per_sample)) == (1/B) * sum_i per_sample[i] * (B - i)
// Single-pass weighted reduction, persistent blocks with dynamic chunk
// stealing (balances per-SM memory-speed spread), last-block finalize.
//
// Determinism: partials are keyed by CHUNK id (value depends only on the
// chunk, block-internal reduce in fixed order); final sum walks chunks in
// fixed index order -> bit-identical output every launch.
// Graph-replay safety: both atomic counters wrap back to 0 each launch
// (chunk counter: exactly NCHUNKS + GRID increments; done counter: GRID).

#define WBCE_EPS 1e-10f
#define GRID_MAIN 888          // 148 SMs * 6 resident blocks
#define THREADS_MAIN 256
#define CHUNK_Q 4096           // float4 groups per chunk (64 KB)
#define MAX_CHUNKS 8192        // N4 = 2^24 -> 4096 chunks

__device__ double g_chunk_sum[MAX_CHUNKS];
__device__ unsigned int g_chunk = 0;   // work counter, self-wrapping
__device__ unsigned int g_done = 0;    // done counter, self-wrapping

__device__ __forceinline__ float elem_term(float l, float t, float wP, float wN) {
    // t is exactly 0.0f or 1.0f; dead branch contributes exactly 0
    bool pos = (t != 0.0f);
    float x = pos ? l : (1.0f - l);
    float w = pos ? wP : wN;
    return w * __logf(x + WBCE_EPS);
}

__global__ __launch_bounds__(THREADS_MAIN, 6) void wbce_fused_kernel(
    const float* __restrict__ logits,
    const float* __restrict__ targets,
    const float* __restrict__ wp,
    const float* __restrict__ wn,
    float* __restrict__ out,
    int N4,          // float4 groups = B*2
    int nchunks,     // ceil(N4 / CHUNK_Q)
    unsigned int grab_wrap)  // nchunks + GRID_MAIN - 1
{
    __shared__ float swp[8];
    __shared__ float swn[8];
    __shared__ int s_chunk;
    __shared__ double ssum[THREADS_MAIN / 32];

    if (threadIdx.x < 8) {
        swp[threadIdx.x] = wp[threadIdx.x];
        swn[threadIdx.x] = wn[threadIdx.x];
    }
    __syncthreads();

    const int t = threadIdx.x;
    // Chunk bases and the 256-thread stride are even -> channel half fixed.
    const int cb = (t & 1) * 4;
    const float w0p = swp[cb + 0], w1p = swp[cb + 1], w2p = swp[cb + 2], w3p = swp[cb + 3];
    const float w0n = swn[cb + 0], w1n = swn[cb + 1], w2n = swn[cb + 2], w3n = swn[cb + 3];

    const float4* __restrict__ lg = (const float4*)logits;
    const float4* __restrict__ tg = (const float4*)targets;
    const int B = N4 >> 1;
    const int warp = t >> 5;

    for (;;) {
        if (t == 0)
            s_chunk = (int)atomicInc(&g_chunk, grab_wrap);
        __syncthreads();   // also orders prior ssum use vs this iteration
        const int chunk = s_chunk;
        if (chunk >= nchunks) break;

        const int base = chunk * CHUNK_Q;
        double acc = 0.0;

        if (base + CHUNK_Q <= N4) {
            // Fast path: full chunk, 16 groups/thread, 8 pair-steps.
            int idx = base + t;
            // Row weight (B - row): integer <= 2^23, exact in fp32.
            float w = (float)(B - (idx >> 1));
            #pragma unroll
            for (int k = 0; k < CHUNK_Q / THREADS_MAIN; k += 2) {
                float4 l0 = __ldg(lg + idx);
                float4 t0 = __ldg(tg + idx);
                float4 l1 = __ldg(lg + idx + THREADS_MAIN);
                float4 t1 = __ldg(tg + idx + THREADS_MAIN);

                float s0 = elem_term(l0.x, t0.x, w0p, w0n)
                         + elem_term(l0.y, t0.y, w1p, w1n)
                         + elem_term(l0.z, t0.z, w2p, w2n)
                         + elem_term(l0.w, t0.w, w3p, w3n);
                float s1 = elem_term(l1.x, t1.x, w0p, w0n)
                         + elem_term(l1.y, t1.y, w1p, w1n)
                         + elem_term(l1.z, t1.z, w2p, w2n)
                         + elem_term(l1.w, t1.w, w3p, w3n);

                // w*s0 + (w-128)*s1 ; one double add per pair
                float prod = fmaf(w, s0, (w - (float)(THREADS_MAIN / 2)) * s1);
                acc -= (double)prod;
                w -= (float)THREADS_MAIN;      // 2 steps * 128 rows
                idx += 2 * THREADS_MAIN;
            }
        } else {
            // Tail chunk (only if N4 % CHUNK_Q != 0)
            for (int idx = base + t; idx < N4; idx += THREADS_MAIN) {
                float4 l0 = __ldg(lg + idx);
                float4 t0 = __ldg(tg + idx);
                float s0 = elem_term(l0.x, t0.x, w0p, w0n)
                         + elem_term(l0.y, t0.y, w1p, w1n)
                         + elem_term(l0.z, t0.z, w2p, w2n)
                         + elem_term(l0.w, t0.w, w3p, w3n);
                float w = (float)(B - (idx >> 1));
                acc -= (double)(w * s0);
            }
        }

        // ---- block reduce this chunk (fixed order -> deterministic) ----
        #pragma unroll
        for (int off = 16; off > 0; off >>= 1)
            acc += __shfl_down_sync(0xffffffffu, acc, off);
        if ((t & 31) == 0) ssum[warp] = acc;
        __syncthreads();
        if (t == 0) {
            double b = 0.0;
            #pragma unroll
            for (int w2 = 0; w2 < THREADS_MAIN / 32; w2++) b += ssum[w2];
            g_chunk_sum[chunk] = b;
        }
        // next-iteration __syncthreads() orders ssum reuse
    }

    // ---- last-block finalize ----
    __shared__ bool s_last;
    if (t == 0) {
        __threadfence();
        unsigned int old = atomicInc(&g_done, GRID_MAIN - 1);  // wraps to 0
        s_last = (old == GRID_MAIN - 1);
    }
    __syncthreads();

    if (s_last) {
        __threadfence();
        volatile double* vp = g_chunk_sum;
        double a = 0.0;
        for (int i = t; i < nchunks; i += THREADS_MAIN)
            a += vp[i];

        #pragma unroll
        for (int off = 16; off > 0; off >>= 1)
            a += __shfl_down_sync(0xffffffffu, a, off);
        if ((t & 31) == 0) ssum[warp] = a;
        __syncthreads();

        if (t == 0) {
            double tot = 0.0;
            #pragma unroll
            for (int w2 = 0; w2 < THREADS_MAIN / 32; w2++) tot += ssum[w2];
            out[0] = (float)(tot / (double)B);
        }
    }
}

extern "C" void kernel_launch(void* const* d_in, const int* in_sizes, int n_in,
                              void* d_out, int out_size) {
    const float* logits  = (const float*)d_in[0];
    const float* targets = (const float*)d_in[1];
    const float* wp      = (const float*)d_in[2];
    const float* wn      = (const float*)d_in[3];

    const int n_elem = in_sizes[0];           // B * 8 = 2^26, fits int32
    const int N4 = n_elem >> 2;               // float4 groups
    int nchunks = (N4 + CHUNK_Q - 1) / CHUNK_Q;
    if (nchunks > MAX_CHUNKS) nchunks = MAX_CHUNKS;  // (not hit for this problem)
    const unsigned int grab_wrap = (unsigned int)(nchunks + GRID_MAIN) - 1u;

    wbce_fused_kernel<<<GRID_MAIN, THREADS_MAIN>>>(logits, targets, wp, wn,
                                                   (float*)d_out, N4, nchunks,
                                                   grab_wrap);
}